// round 12
// baseline (speedup 1.0000x reference)
#include <cuda_runtime.h>
#include <cstdint>

// EdgeEmbedding: out[i, :] = edge_type_embedding[data[i], :] + type_attr_sum[data[i], :]
//
//   comb[t, :] = ete[t, :] + segment_sum(attr_table[flat_attr_ids], attr_seg_ids)[t, :]
//   out[i, :]  = comb[data[i], :]
//
// R3 change (unbenched R4-R11, broker timeouts; resubmitting): gather rows are
// written with per-thread cp.async.bulk (1 KB smem -> global DMA) instead of a
// warp-serialized shfl + STG.128 copy loop. Each thread owns one edge;
// in-slice edges fire one bulk copy. Source rows in smem are immutable during
// the scan, so the only synchronization needed is bounding the bulk-group
// queue and draining before exit.

#define NUM_TYPES 1000
#define DIM 256
#define DIM4 (DIM / 4)          // 64 float4 per row
#define ROW_BYTES 1024

#define TYPES_PER_SLICE 200
#define NUM_SLICES 5            // 5 * 200 = 1000
#define BLOCKS_PER_SLICE 29     // 5 * 29 = 145 CTAs ~ one per SM
#define GATHER_THREADS 512
#define SLICE_SMEM_BYTES (TYPES_PER_SLICE * DIM * sizeof(float))  // 204800

__device__ float g_comb[NUM_TYPES * DIM];

// ---------------------------------------------------------------------------
// Phase 1: comb[t, d] = edge_type_embedding[t, d]
// ---------------------------------------------------------------------------
__global__ void init_comb_kernel(const float* __restrict__ ete) {
    int idx = blockIdx.x * blockDim.x + threadIdx.x;
    if (idx < NUM_TYPES * DIM4) {
        const float4* src = reinterpret_cast<const float4*>(ete);
        float4* dst = reinterpret_cast<float4*>(g_comb);
        dst[idx] = src[idx];
    }
}

// ---------------------------------------------------------------------------
// Phase 2: comb[seg[a], d] += attr_table[id[a], d]   (atomic segment sum)
// ---------------------------------------------------------------------------
__global__ void segsum_kernel(const float* __restrict__ attr_table,
                              const int* __restrict__ flat_attr_ids,
                              const int* __restrict__ attr_seg_ids,
                              int total_attrs) {
    int gid = blockIdx.x * blockDim.x + threadIdx.x;
    int total = total_attrs * DIM4;
    if (gid >= total) return;
    int a = gid >> 6;           // attr index
    int c = gid & (DIM4 - 1);   // float4 chunk within row
    int id  = flat_attr_ids[a];
    int seg = attr_seg_ids[a];
    float4 v = reinterpret_cast<const float4*>(attr_table)[(long long)id * DIM4 + c];
    float* dst = &g_comb[seg * DIM + c * 4];
    atomicAdd(dst + 0, v.x);
    atomicAdd(dst + 1, v.y);
    atomicAdd(dst + 2, v.z);
    atomicAdd(dst + 3, v.w);
}

// ---------------------------------------------------------------------------
// cp.async.bulk helpers (smem -> global, per-thread bulk-group)
// ---------------------------------------------------------------------------
__device__ __forceinline__ void bulk_store_row(void* gdst, uint32_t ssrc) {
    asm volatile(
        "cp.async.bulk.global.shared::cta.bulk_group [%0], [%1], %2;"
        :: "l"(gdst), "r"(ssrc), "n"(ROW_BYTES) : "memory");
}
__device__ __forceinline__ void bulk_commit() {
    asm volatile("cp.async.bulk.commit_group;" ::: "memory");
}
template <int N>
__device__ __forceinline__ void bulk_wait() {
    asm volatile("cp.async.bulk.wait_group %0;" :: "n"(N) : "memory");
}

// ---------------------------------------------------------------------------
// Phase 3: smem-sliced gather with DMA row stores.
// CTA (slice, b): load comb[slice*200 .. +200) into smem, scan edge chunk b.
// Each thread owns one edge per iteration; if data[e] is in-slice it issues a
// 1 KB cp.async.bulk from its smem row to out[e]. Union of slices covers all
// types -> each edge written exactly once.
// ---------------------------------------------------------------------------
__global__ void __launch_bounds__(GATHER_THREADS, 1)
gather_smem_kernel(const int* __restrict__ data,
                   float* __restrict__ out,
                   int n) {
    extern __shared__ float4 s_comb[];   // TYPES_PER_SLICE * 64 float4

    int slice = blockIdx.x / BLOCKS_PER_SLICE;
    int b     = blockIdx.x % BLOCKS_PER_SLICE;
    int t_lo  = slice * TYPES_PER_SLICE;
    int t_hi  = t_lo + TYPES_PER_SLICE;
    if (t_hi > NUM_TYPES) t_hi = NUM_TYPES;
    int nt = t_hi - t_lo;

    // Load this slice of comb into shared memory (fully coalesced float4).
    const float4* comb4 = reinterpret_cast<const float4*>(g_comb);
    for (int i = threadIdx.x; i < nt * DIM4; i += GATHER_THREADS)
        s_comb[i] = comb4[t_lo * DIM4 + i];
    __syncthreads();

    // smem base address (32-bit shared window) for bulk-copy source addressing.
    uint32_t s_base;
    asm("{ .reg .u64 t; cvta.to.shared.u64 t, %1; cvt.u32.u64 %0, t; }"
        : "=r"(s_base) : "l"((const void*)s_comb));

    // Edge chunk for this b (scanned by all 5 slices).
    int chunk = (n + BLOCKS_PER_SLICE - 1) / BLOCKS_PER_SLICE;
    int e0 = b * chunk;
    int e1 = e0 + chunk;
    if (e1 > n) e1 = n;

    for (int e = e0 + threadIdx.x; e < e1; e += GATHER_THREADS) {
        int t = __ldg(&data[e]);
        if (t >= t_lo && t < t_hi) {
            uint32_t src = s_base + (uint32_t)(t - t_lo) * ROW_BYTES;
            void* dst = (void*)(out + (long long)e * DIM);
            bulk_store_row(dst, src);
        }
        bulk_commit();
        bulk_wait<6>();   // bound the in-flight DMA queue (~6 KB/thread max)
    }
    // Drain all outstanding bulk stores before the CTA (and its smem) retires.
    bulk_commit();
    bulk_wait<0>();
}

// ---------------------------------------------------------------------------
// Launch. Inputs (metadata order):
//   d_in[0] data              [N]           int32
//   d_in[1] attr_table        [200000*256]  float32
//   d_in[2] edge_type_embed   [1000*256]    float32
//   d_in[3] flat_attr_ids     [50000]       int32
//   d_in[4] attr_seg_ids      [50000]       int32
// out: [N*256] float32
// ---------------------------------------------------------------------------
extern "C" void kernel_launch(void* const* d_in, const int* in_sizes, int n_in,
                              void* d_out, int out_size) {
    const int*   data        = (const int*)d_in[0];
    const float* attr_table  = (const float*)d_in[1];
    const float* ete         = (const float*)d_in[2];
    const int*   flat_ids    = (const int*)d_in[3];
    const int*   seg_ids     = (const int*)d_in[4];
    float*       out         = (float*)d_out;

    int n           = in_sizes[0];
    int total_attrs = in_sizes[3];

    // One-time-per-call attribute set (idempotent, host-side, pre-capture).
    static bool attr_set = false;
    if (!attr_set) {
        cudaFuncSetAttribute(gather_smem_kernel,
                             cudaFuncAttributeMaxDynamicSharedMemorySize,
                             SLICE_SMEM_BYTES);
        attr_set = true;
    }

    // Phase 1: init comb with edge-type embedding
    {
        int work = NUM_TYPES * DIM4;
        init_comb_kernel<<<(work + 255) / 256, 256>>>(ete);
    }
    // Phase 2: atomic segment sum of attr embeddings into comb
    {
        int work = total_attrs * DIM4;
        segsum_kernel<<<(work + 255) / 256, 256>>>(attr_table, flat_ids, seg_ids,
                                                   total_attrs);
    }
    // Phase 3: smem-sliced gather with DMA row stores (HBM-write-bound)
    {
        gather_smem_kernel<<<NUM_SLICES * BLOCKS_PER_SLICE, GATHER_THREADS,
                             SLICE_SMEM_BYTES>>>(data, out, n);
    }
}